// round 6
// baseline (speedup 1.0000x reference)
#include <cuda_runtime.h>
#include <cuda_bf16.h>
#include <math.h>

typedef unsigned long long ull;

// ---------------- constants ----------------
#define T_LEN 512
#define B_SZ  64
#define E_DIM 256
#define H_DIM 256
#define S_ST  64
#define G4H   1024   // 4*H

// gred layout: ull index = rp*82 + slot*10 + c   (rp 0..63, slot 0..7, c 0..7)
#define GRED_RP 82
#define GRED_SL 10
#define GRED_SZ (64 * GRED_RP)

// ---------------- device scratch ----------------
__device__ float g_xg[2][T_LEN][B_SZ][G4H];   // precomputed x-gates + bias (chain-step order)
__device__ float g_h[T_LEN * B_SZ][2 * H_DIM]; // BiLSTM features
__device__ float g_sc[T_LEN * B_SZ][S_ST];     // emission scores (incl b_lin)

// ---------------- helpers ----------------
__device__ __forceinline__ ull pk2(float x, float y) {
    ull r; asm("mov.b64 %0, {%1,%2};" : "=l"(r) : "f"(x), "f"(y)); return r;
}
__device__ __forceinline__ void upk2(ull v, float& x, float& y) {
    asm("mov.b64 {%0,%1}, %2;" : "=f"(x), "=f"(y) : "l"(v));
}
__device__ __forceinline__ ull fma2_(ull a, ull b, ull c) {
    ull d; asm("fma.rn.f32x2 %0, %1, %2, %3;" : "=l"(d) : "l"(a), "l"(b), "l"(c)); return d;
}
__device__ __forceinline__ ull add2_(ull a, ull b) {
    ull d; asm("add.rn.f32x2 %0, %1, %2;" : "=l"(d) : "l"(a), "l"(b)); return d;
}
__device__ __forceinline__ unsigned smem_u32(const void* p) {
    unsigned a;
    asm("{ .reg .u64 t; cvta.to.shared.u64 t, %1; cvt.u32.u64 %0, t; }" : "=r"(a) : "l"(p));
    return a;
}
__device__ __forceinline__ unsigned mapa_(unsigned addr, unsigned rank) {
    unsigned r; asm("mapa.shared::cluster.u32 %0, %1, %2;" : "=r"(r) : "r"(addr), "r"(rank));
    return r;
}
#define CLUSTER_SYNC() do { \
    asm volatile("barrier.cluster.arrive.aligned;" ::: "memory"); \
    asm volatile("barrier.cluster.wait.aligned;"   ::: "memory"); \
} while (0)

#define MBAR_INIT(addr, cnt) \
    asm volatile("mbarrier.init.shared.b64 [%0], %1;" :: "r"(addr), "r"(cnt) : "memory")
#define MBAR_INVAL(addr) \
    asm volatile("mbarrier.inval.shared.b64 [%0];" :: "r"(addr) : "memory")
#define MBAR_EXPECT_TX(addr, tx) \
    asm volatile("mbarrier.arrive.expect_tx.shared.b64 _, [%0], %1;" \
                 :: "r"(addr), "r"(tx) : "memory")
#define MBAR_ARRIVE_CLUSTER(raddr) \
    asm volatile("mbarrier.arrive.shared::cluster.b64 _, [%0];" :: "r"(raddr) : "memory")

#define MBAR_WAIT(addr, parity) do { \
    unsigned _mb = (addr); unsigned _ph = (parity); unsigned _done; \
    asm volatile("{\n\t.reg .pred p;\n\t" \
        "mbarrier.try_wait.parity.acquire.cta.shared::cta.b64 p, [%1], %2;\n\t" \
        "selp.b32 %0, 1, 0, p;\n\t}" : "=r"(_done) : "r"(_mb), "r"(_ph) : "memory"); \
    if (!_done) { \
        asm volatile("{\n\t.reg .pred P1;\n\t" \
            "WL_%=:\n\t" \
            "mbarrier.try_wait.parity.acquire.cta.shared::cta.b64 P1, [%0], %1, 0x989680;\n\t" \
            "@P1 bra.uni WD_%=;\n\t" \
            "bra.uni WL_%=;\n\t" \
            "WD_%=:\n\t}" :: "r"(_mb), "r"(_ph) : "memory"); \
    } \
} while (0)

#define BULK_S2S(dst, src, bytes, mbar) \
    asm volatile("cp.async.bulk.shared::cluster.shared::cta.mbarrier::complete_tx::bytes " \
                 "[%0], [%1], %2, [%3];" \
                 :: "r"(dst), "r"(src), "r"(bytes), "r"(mbar) : "memory")

__device__ __forceinline__ float sgm(float x) { return 1.0f / (1.0f + expf(-x)); }
__device__ __forceinline__ float tanh_(float x) { return 1.0f - 2.0f / (expf(2.0f * x) + 1.0f); }

// =====================================================================
// Kernel A: x-gates GEMM. BM=128, BN=128, BK=16, 256 thr, 8x8 micro.
//   xg[dir][s][b][g] = emb[obs[t,b]] . Wih_dir[g,:] + bih[g]+bhh[g]
// =====================================================================
__global__ void __launch_bounds__(256) kA(
    const int* __restrict__ obs, const float* __restrict__ emb,
    const float* __restrict__ WihF, const float* __restrict__ WihB,
    const float* __restrict__ bihF, const float* __restrict__ bhhF,
    const float* __restrict__ bihB, const float* __restrict__ bhhB)
{
    __shared__ float As[16][132];
    __shared__ float Bs[16][132];
    __shared__ int rowidx[128];

    const int tid = threadIdx.x;
    const int mBase = blockIdx.x * 128;
    const int nTile = blockIdx.y;            // 0..15
    const int dir = nTile >> 3;
    const int nBase = (nTile & 7) * 128;     // within [0,1024)
    const float* W = dir ? WihB : WihF;

    if (tid < 128) rowidx[tid] = obs[mBase + tid];
    __syncthreads();

    const int ty = tid >> 4;   // 0..15 row-groups of 8
    const int tx = tid & 15;   // 0..15 col-groups of 8

    ull acc[4][8];
#pragma unroll
    for (int m = 0; m < 4; m++)
#pragma unroll
        for (int j = 0; j < 8; j++) acc[m][j] = 0ull;

    const int lrow = tid >> 1, lkq = tid & 1;   // loader: row/n, k-half

    for (int kt = 0; kt < 16; ++kt) {
        {
            const float4 va0 = *reinterpret_cast<const float4*>(
                &emb[(size_t)rowidx[lrow] * E_DIM + kt * 16 + lkq * 8]);
            const float4 va1 = *reinterpret_cast<const float4*>(
                &emb[(size_t)rowidx[lrow] * E_DIM + kt * 16 + lkq * 8 + 4]);
            As[lkq * 8 + 0][lrow] = va0.x; As[lkq * 8 + 1][lrow] = va0.y;
            As[lkq * 8 + 2][lrow] = va0.z; As[lkq * 8 + 3][lrow] = va0.w;
            As[lkq * 8 + 4][lrow] = va1.x; As[lkq * 8 + 5][lrow] = va1.y;
            As[lkq * 8 + 6][lrow] = va1.z; As[lkq * 8 + 7][lrow] = va1.w;
            const float4 vb0 = *reinterpret_cast<const float4*>(
                &W[(size_t)(nBase + lrow) * E_DIM + kt * 16 + lkq * 8]);
            const float4 vb1 = *reinterpret_cast<const float4*>(
                &W[(size_t)(nBase + lrow) * E_DIM + kt * 16 + lkq * 8 + 4]);
            Bs[lkq * 8 + 0][lrow] = vb0.x; Bs[lkq * 8 + 1][lrow] = vb0.y;
            Bs[lkq * 8 + 2][lrow] = vb0.z; Bs[lkq * 8 + 3][lrow] = vb0.w;
            Bs[lkq * 8 + 4][lrow] = vb1.x; Bs[lkq * 8 + 5][lrow] = vb1.y;
            Bs[lkq * 8 + 6][lrow] = vb1.z; Bs[lkq * 8 + 7][lrow] = vb1.w;
        }
        __syncthreads();
#pragma unroll
        for (int k = 0; k < 16; ++k) {
            float4 a0 = *reinterpret_cast<const float4*>(&As[k][ty * 8]);
            float4 a1 = *reinterpret_cast<const float4*>(&As[k][ty * 8 + 4]);
            float4 b0 = *reinterpret_cast<const float4*>(&Bs[k][tx * 8]);
            float4 b1 = *reinterpret_cast<const float4*>(&Bs[k][tx * 8 + 4]);
            ull ap[4] = {pk2(a0.x, a0.y), pk2(a0.z, a0.w), pk2(a1.x, a1.y), pk2(a1.z, a1.w)};
            ull bd[8] = {pk2(b0.x, b0.x), pk2(b0.y, b0.y), pk2(b0.z, b0.z), pk2(b0.w, b0.w),
                         pk2(b1.x, b1.x), pk2(b1.y, b1.y), pk2(b1.z, b1.z), pk2(b1.w, b1.w)};
#pragma unroll
            for (int m = 0; m < 4; ++m)
#pragma unroll
                for (int j = 0; j < 8; ++j)
                    acc[m][j] = fma2_(ap[m], bd[j], acc[m][j]);
        }
        __syncthreads();
    }

    // epilogue: +bias, scatter (fwd as-is, bwd time-reversed)
    const int n0 = nBase + tx * 8;
    const float* bi = dir ? bihB : bihF;
    const float* bh = dir ? bhhB : bhhF;
    float bias[8];
#pragma unroll
    for (int j = 0; j < 8; ++j) bias[j] = bi[n0 + j] + bh[n0 + j];
#pragma unroll
    for (int m = 0; m < 4; ++m) {
        float lo[8], hi[8];
#pragma unroll
        for (int j = 0; j < 8; ++j) upk2(acc[m][j], lo[j], hi[j]);
        int mg0 = mBase + ty * 8 + 2 * m;
#pragma unroll
        for (int r = 0; r < 2; ++r) {
            int mg = mg0 + r;
            int t = mg >> 6, b = mg & 63;
            int sIdx = dir ? (T_LEN - 1 - t) : t;
            const float* src = r ? hi : lo;
            float* dst = &g_xg[dir][sIdx][b][n0];
            *reinterpret_cast<float4*>(dst) =
                make_float4(src[0] + bias[0], src[1] + bias[1], src[2] + bias[2], src[3] + bias[3]);
            *reinterpret_cast<float4*>(dst + 4) =
                make_float4(src[4] + bias[4], src[5] + bias[5], src[6] + bias[6], src[7] + bias[7]);
        }
    }
}

// =====================================================================
// Kernel B: recurrence, two interleaved chains, FUSED reduce+cell
// (2 barriers per chain step, no gfull).
// =====================================================================
struct SmemB {
    float hbuf[2][2][H_DIM][8];  // [chain][pingpong][k][batch]   32768 B
    ull   gred[GRED_SZ];         // rp*82 + slot*10 + c           41984 B
    float hstage[2][2][256];     // [chain][pingpong][u*8+bb]      4096 B
    ull   mb_full[2][2];
    ull   mb_go[2][2];
};

__global__ void __launch_bounds__(512, 1) __cluster_dims__(8, 1, 1) kB(
    const float* __restrict__ WhhF, const float* __restrict__ WhhB,
    const float* __restrict__ h0, const float* __restrict__ c0)
{
    extern __shared__ char smraw[];
    SmemB& sm = *reinterpret_cast<SmemB*>(smraw);

    const int tid = threadIdx.x;
    const int blk = blockIdx.x;
    const int cr = blk & 7;
    const int cid = blk >> 3;          // 0..7
    const int dir = cid >> 2;
    const int bgp = cid & 3;
    const int b0A = bgp * 16;          // chain 0 batches; chain 1 = +8
    const float* Whh = dir ? WhhB : WhhF;
    const float* xg = &g_xg[dir][0][0][0];

    // ---- GEMV role ----
    const int c = tid >> 6;
    const int rp = tid & 63;
    const int jA = 2 * rp, jB = 2 * rp + 1;
    const int rgA = ((jA >> 5) << 8) + (cr << 5) + (jA & 31);
    const int rgB = ((jB >> 5) << 8) + (cr << 5) + (jB & 31);

    float wA[32], wB[32];
    {
        const float4* pA = reinterpret_cast<const float4*>(&Whh[(size_t)rgA * H_DIM + 32 * c]);
        const float4* pB = reinterpret_cast<const float4*>(&Whh[(size_t)rgB * H_DIM + 32 * c]);
#pragma unroll
        for (int qq = 0; qq < 8; ++qq) {
            float4 va = pA[qq], vb = pB[qq];
            wA[qq * 4 + 0] = va.x; wA[qq * 4 + 1] = va.y; wA[qq * 4 + 2] = va.z; wA[qq * 4 + 3] = va.w;
            wB[qq * 4 + 0] = vb.x; wB[qq * 4 + 1] = vb.y; wB[qq * 4 + 2] = vb.z; wB[qq * 4 + 3] = vb.w;
        }
    }

    // ---- fused reduce+cell role: pair (even: i,f | odd: g,o) per (u,bb) ----
    const int cid2 = tid >> 1, par = tid & 1;
    const int uF = cid2 >> 3, bbF = cid2 & 7;
    const int mF = bbF >> 1, selF = bbF & 1;
    const int row1 = par ? (64 + uF) : uF;
    const int row2 = row1 + 32;
    const int rg1 = ((row1 >> 5) << 8) + (cr << 5) + (row1 & 31);
    const int rg2 = ((row2 >> 5) << 8) + (cr << 5) + (row2 & 31);
    const int gbase1 = (row1 >> 1) * GRED_RP + ((uF & 1) * 4 + mF) * GRED_SL;
    const int gbase2 = (row2 >> 1) * GRED_RP + ((uF & 1) * 4 + mF) * GRED_SL;
    const float* pX1 = xg + (size_t)(b0A + bbF) * G4H + rg1;   // chain 1: +8*G4H
    const float* pX2 = xg + (size_t)(b0A + bbF) * G4H + rg2;

    // ---- init hbuf[ch][0] ----
    for (int idx = tid; idx < 4096; idx += 512) {
        int ch = idx >> 11, r2 = idx & 2047;
        int k = r2 >> 3, bb = r2 & 7;
        sm.hbuf[ch][0][k][bb] = h0[((size_t)dir * B_SZ + b0A + ch * 8 + bb) * H_DIM + k];
    }

    // ---- cell state on even threads ----
    float c_reg[2] = {0.f, 0.f};
    if (par == 0) {
        c_reg[0] = c0[((size_t)dir * B_SZ + b0A + bbF) * H_DIM + cr * 32 + uF];
        c_reg[1] = c0[((size_t)dir * B_SZ + b0A + 8 + bbF) * H_DIM + cr * 32 + uF];
    }

    // ---- messenger addresses ----
    unsigned goL[2][2], fullL[2][2], dstL[2][2];
#pragma unroll
    for (int ch = 0; ch < 2; ++ch)
#pragma unroll
        for (int pp = 0; pp < 2; ++pp) {
            goL[ch][pp]   = smem_u32(&sm.mb_go[ch][pp]);
            fullL[ch][pp] = smem_u32(&sm.mb_full[ch][pp]);
            dstL[ch][pp]  = smem_u32(&sm.hbuf[ch][pp][cr * 32][0]);
        }

    // ---- h gmem store role (tid < 64) ----
    const int sb = tid >> 3, skq = tid & 7;

    if (tid == 0) {
#pragma unroll
        for (int ch = 0; ch < 2; ++ch) {
            MBAR_INIT(fullL[ch][0], 1); MBAR_INIT(fullL[ch][1], 1);
            MBAR_INIT(goL[ch][0], 8);   MBAR_INIT(goL[ch][1], 8);
            MBAR_EXPECT_TX(fullL[ch][1], 7168);
        }
    }
    __syncthreads();
    CLUSTER_SYNC();

    if (tid == 0) {
#pragma unroll
        for (int ch = 0; ch < 2; ++ch)
#pragma unroll
            for (int j = 0; j < 8; ++j)
                MBAR_ARRIVE_CLUSTER(mapa_(goL[ch][1], (unsigned)j));
    }

    unsigned phF[2] = {0, 0};
    unsigned phG[2] = {0, 0};

    for (int s = 0; s < T_LEN; ++s) {
        const int p = s & 1, q = p ^ 1;

#pragma unroll
        for (int ch = 0; ch < 2; ++ch) {
            const unsigned fullLp = fullL[ch][p];

            if (s > 0) {
                MBAR_WAIT(fullLp, (phF[ch] >> p) & 1);
                phF[ch] ^= (1u << p);
            }

            // prefetch xg for the fused phase (hidden behind GEMV)
            const size_t xoff = (size_t)s * B_SZ * G4H + (size_t)ch * 8 * G4H;
            const float xv1 = pX1[xoff];
            const float xv2 = pX2[xoff];

            // ---- GEMV (weights in regs, LDS.128 h) ----
            ull aA0 = 0, aA1 = 0, aA2 = 0, aA3 = 0;
            ull aB0 = 0, aB1 = 0, aB2 = 0, aB3 = 0;
            const ulonglong2* hp2 =
                reinterpret_cast<const ulonglong2*>(&sm.hbuf[ch][p][32 * c][0]);
#pragma unroll
            for (int k = 0; k < 32; ++k) {
                ulonglong2 hA = hp2[k * 2 + 0];
                ulonglong2 hB = hp2[k * 2 + 1];
                ull wa = pk2(wA[k], wA[k]);
                ull wb = pk2(wB[k], wB[k]);
                aA0 = fma2_(wa, hA.x, aA0); aA1 = fma2_(wa, hA.y, aA1);
                aA2 = fma2_(wa, hB.x, aA2); aA3 = fma2_(wa, hB.y, aA3);
                aB0 = fma2_(wb, hA.x, aB0); aB1 = fma2_(wb, hA.y, aB1);
                aB2 = fma2_(wb, hB.x, aB2); aB3 = fma2_(wb, hB.y, aB3);
            }
            {
                ull* g = &sm.gred[rp * GRED_RP + c];
                g[0 * GRED_SL] = aA0;  // even rows, slot m
                g[1 * GRED_SL] = aA1;
                g[2 * GRED_SL] = aA2;
                g[3 * GRED_SL] = aA3;
                g[4 * GRED_SL] = aB0;  // odd rows, slot 4+m
                g[5 * GRED_SL] = aB1;
                g[6 * GRED_SL] = aB2;
                g[7 * GRED_SL] = aB3;
            }
            __syncthreads();   // bar1: gred ready, hbuf[ch][p] reads done

            if (tid == 0 && s < T_LEN - 1) {
                MBAR_EXPECT_TX(fullLp, 7168);
#pragma unroll
                for (int j = 0; j < 8; ++j)
                    MBAR_ARRIVE_CLUSTER(mapa_(goL[ch][p], (unsigned)j));
            }

            // ---- FUSED reduce + cell ----
            {
                const ulonglong2* v1 = reinterpret_cast<const ulonglong2*>(&sm.gred[gbase1]);
                ulonglong2 a = v1[0], b = v1[1], cc2 = v1[2], d = v1[3];
                ull r1 = add2_(add2_(add2_(a.x, a.y), add2_(b.x, b.y)),
                               add2_(add2_(cc2.x, cc2.y), add2_(d.x, d.y)));
                const ulonglong2* v2 = reinterpret_cast<const ulonglong2*>(&sm.gred[gbase2]);
                ulonglong2 e = v2[0], f = v2[1], g2 = v2[2], h2 = v2[3];
                ull r2 = add2_(add2_(add2_(e.x, e.y), add2_(f.x, f.y)),
                               add2_(add2_(g2.x, g2.y), add2_(h2.x, h2.y)));
                float lo, hi;
                upk2(r1, lo, hi);
                float gate1 = (selF ? hi : lo) + xv1;   // par0: i ; par1: g
                upk2(r2, lo, hi);
                float gate2 = (selF ? hi : lo) + xv2;   // par0: f ; par1: o

                float va, vb;
                if (par == 0) { va = sgm(gate1);  vb = sgm(gate2); }   // sgm(i), sgm(f)
                else          { va = tanh_(gate1); vb = sgm(gate2); }  // tanh(g), sgm(o)

                float gvr = __shfl_xor_sync(0xffffffffu, va, 1); // even gets tanh(g)
                float cnew = vb * c_reg[ch] + va * gvr;          // valid on even
                if (par == 0) c_reg[ch] = cnew;
                float cr2 = __shfl_xor_sync(0xffffffffu, cnew, 1); // odd gets cnew
                if (par == 1) {
                    float hv = vb * tanh_(cr2);
                    sm.hstage[ch][p][cid2] = hv;
                    sm.hbuf[ch][q][cr * 32 + uF][bbF] = hv;   // self-slice
                }
            }
            __syncthreads();   // bar2: hstage + self-slice visible

            if (tid == 0 && s < T_LEN - 1) {
                asm volatile("fence.proxy.async.shared::cta;" ::: "memory");
                MBAR_WAIT(goL[ch][q], (phG[ch] >> q) & 1);
                phG[ch] ^= (1u << q);
                const unsigned src = smem_u32(&sm.hstage[ch][p][0]);
#pragma unroll
                for (int j = 0; j < 8; ++j) {
                    if (j == cr) continue;
                    unsigned dst = mapa_(dstL[ch][q], (unsigned)j);
                    unsigned mb = mapa_(fullL[ch][q], (unsigned)j);
                    BULK_S2S(dst, src, 1024u, mb);
                }
            }

            if (tid < 64) {
                float4 o;
                o.x = sm.hstage[ch][p][(skq * 4 + 0) * 8 + sb];
                o.y = sm.hstage[ch][p][(skq * 4 + 1) * 8 + sb];
                o.z = sm.hstage[ch][p][(skq * 4 + 2) * 8 + sb];
                o.w = sm.hstage[ch][p][(skq * 4 + 3) * 8 + sb];
                int tOut = dir ? (T_LEN - 1 - s) : s;
                *reinterpret_cast<float4*>(
                    &g_h[(size_t)tOut * B_SZ + b0A + ch * 8 + sb][dir * H_DIM + cr * 32 + skq * 4]) = o;
            }
        }
    }

    CLUSTER_SYNC();
    if (tid == 0) {
#pragma unroll
        for (int ch = 0; ch < 2; ++ch) {
            MBAR_INVAL(fullL[ch][0]); MBAR_INVAL(fullL[ch][1]);
            MBAR_INVAL(goL[ch][0]);   MBAR_INVAL(goL[ch][1]);
        }
    }
}

// =====================================================================
// Kernel S: emission scores GEMM (unchanged).
// =====================================================================
__global__ void __launch_bounds__(256) kS(
    const float* __restrict__ Wlin, const float* __restrict__ blin)
{
    __shared__ float As[32][132];
    __shared__ float Bs[32][68];

    const int tid = threadIdx.x;
    const int mBase = blockIdx.x * 128;

    const int ty = tid >> 4;
    const int tx = tid & 15;

    ull acc[4][4];
#pragma unroll
    for (int m = 0; m < 4; m++)
#pragma unroll
        for (int j = 0; j < 4; j++) acc[m][j] = 0ull;

    const int arow = tid >> 3, akq = tid & 7;
    const int bn = tid >> 2, bkq = tid & 3;

    for (int kt = 0; kt < 16; ++kt) {
#pragma unroll
        for (int rr = 0; rr < 4; ++rr) {
            int r = arow + rr * 32;
            const float4 v = *reinterpret_cast<const float4*>(
                &g_h[mBase + r][kt * 32 + akq * 4]);
            As[akq * 4 + 0][r] = v.x; As[akq * 4 + 1][r] = v.y;
            As[akq * 4 + 2][r] = v.z; As[akq * 4 + 3][r] = v.w;
        }
#pragma unroll
        for (int hh = 0; hh < 2; ++hh) {
            const float4 v = *reinterpret_cast<const float4*>(
                &Wlin[(size_t)bn * (2 * H_DIM) + kt * 32 + bkq * 8 + hh * 4]);
            Bs[bkq * 8 + hh * 4 + 0][bn] = v.x; Bs[bkq * 8 + hh * 4 + 1][bn] = v.y;
            Bs[bkq * 8 + hh * 4 + 2][bn] = v.z; Bs[bkq * 8 + hh * 4 + 3][bn] = v.w;
        }
        __syncthreads();
#pragma unroll 8
        for (int k = 0; k < 32; ++k) {
            float4 a0 = *reinterpret_cast<const float4*>(&As[k][ty * 8]);
            float4 a1 = *reinterpret_cast<const float4*>(&As[k][ty * 8 + 4]);
            float4 b4 = *reinterpret_cast<const float4*>(&Bs[k][tx * 4]);
            ull ap[4] = {pk2(a0.x, a0.y), pk2(a0.z, a0.w), pk2(a1.x, a1.y), pk2(a1.z, a1.w)};
            ull bd[4] = {pk2(b4.x, b4.x), pk2(b4.y, b4.y), pk2(b4.z, b4.z), pk2(b4.w, b4.w)};
#pragma unroll
            for (int m = 0; m < 4; ++m)
#pragma unroll
                for (int j = 0; j < 4; ++j)
                    acc[m][j] = fma2_(ap[m], bd[j], acc[m][j]);
        }
        __syncthreads();
    }

    const int n0 = tx * 4;
    float bias[4];
#pragma unroll
    for (int j = 0; j < 4; ++j) bias[j] = blin[n0 + j];
#pragma unroll
    for (int m = 0; m < 4; ++m) {
        float lo[4], hi[4];
#pragma unroll
        for (int j = 0; j < 4; ++j) upk2(acc[m][j], lo[j], hi[j]);
        int row0 = mBase + ty * 8 + 2 * m;
#pragma unroll
        for (int r = 0; r < 2; ++r) {
            const float* src = r ? hi : lo;
            float4 o = make_float4(src[0] + bias[0], src[1] + bias[1],
                                   src[2] + bias[2], src[3] + bias[3]);
            *reinterpret_cast<float4*>(&g_sc[row0 + r][n0]) = o;
        }
    }
}

// =====================================================================
// Kernel C: Viterbi DP + backtrace. REDUX-based exact first-max merge.
// =====================================================================
__device__ __forceinline__ unsigned fmap(float v) {
    unsigned u = __float_as_uint(v);
    return (u & 0x80000000u) ? ~u : (u | 0x80000000u);
}
__device__ __forceinline__ float funmap(unsigned u) {
    unsigned x = (u & 0x80000000u) ? (u ^ 0x80000000u) : ~u;
    return __uint_as_float(x);
}

__global__ void __launch_bounds__(512) kC(
    const float* __restrict__ pw,
    const float* __restrict__ startv, const float* __restrict__ stopv,
    float* __restrict__ out)
{
    __shared__ float delta[2][64];
    __shared__ float fin[64];
    __shared__ unsigned char bp[T_LEN - 1][64];

    const int b = blockIdx.x;
    const int tid = threadIdx.x;
    const int s = tid >> 3;      // state 0..63
    const int p = tid & 7;       // part 0..7

    float Pr[8];
#pragma unroll
    for (int i = 0; i < 8; ++i) Pr[i] = pw[(p * 8 + i) * 64 + s];

    const unsigned gmask = 0xFFu << (((tid & 31) >> 3) << 3);

    if (p == 0) delta[0][s] = startv[s] + g_sc[b][s];
    __syncthreads();

    float scN = g_sc[(size_t)1 * B_SZ + b][s];
    for (int t = 1; t < T_LEN; ++t) {
        const int pp = (t - 1) & 1, qq = t & 1;
        float4 d0 = *reinterpret_cast<const float4*>(&delta[pp][p * 8]);
        float4 d1 = *reinterpret_cast<const float4*>(&delta[pp][p * 8 + 4]);
        float dv[8] = {d0.x, d0.y, d0.z, d0.w, d1.x, d1.y, d1.z, d1.w};

        float best = dv[0] + Pr[0];
        int bi = p * 8;
#pragma unroll
        for (int i = 1; i < 8; ++i) {
            float v = dv[i] + Pr[i];
            if (v > best) { best = v; bi = p * 8 + i; }
        }
        // exact first-max across the 8 parts via 2 REDUX ops
        unsigned mv = fmap(best);
        unsigned vmax = __reduce_max_sync(gmask, mv);
        unsigned cand = (mv == vmax) ? (unsigned)bi : 1000u;
        unsigned bidx = __reduce_min_sync(gmask, cand);

        const float sc = scN;
        if (t < T_LEN - 1) scN = g_sc[(size_t)(t + 1) * B_SZ + b][s];

        if (p == 0) {
            bp[t - 1][s] = (unsigned char)bidx;
            delta[qq][s] = funmap(vmax) + sc;
        }
        __syncthreads();
    }

    if (p == 0) fin[s] = delta[(T_LEN - 1) & 1][s] + stopv[s];
    __syncthreads();

    if (tid == 0) {
        float best = fin[0]; int bi0 = 0;
        for (int i = 1; i < 64; ++i) if (fin[i] > best) { best = fin[i]; bi0 = i; }
        out[b] = best;
        int st = bi0;
        out[64 + (size_t)(T_LEN - 1) * B_SZ + b] = (float)st;
        for (int tt = T_LEN - 2; tt >= 0; --tt) {
            st = bp[tt][st];
            out[64 + (size_t)tt * B_SZ + b] = (float)st;
        }
    }
}

// =====================================================================
extern "C" void kernel_launch(void* const* d_in, const int* in_sizes, int n_in,
                              void* d_out, int out_size)
{
    const int*   obs  = (const int*)  d_in[0];
    const float* h0   = (const float*)d_in[1];
    const float* c0   = (const float*)d_in[2];
    const float* emb  = (const float*)d_in[3];
    const float* WihF = (const float*)d_in[4];
    const float* WhhF = (const float*)d_in[5];
    const float* bihF = (const float*)d_in[6];
    const float* bhhF = (const float*)d_in[7];
    const float* WihB = (const float*)d_in[8];
    const float* WhhB = (const float*)d_in[9];
    const float* bihB = (const float*)d_in[10];
    const float* bhhB = (const float*)d_in[11];
    const float* Wlin = (const float*)d_in[12];
    const float* blin = (const float*)d_in[13];
    const float* pw   = (const float*)d_in[14];
    const float* stv  = (const float*)d_in[15];
    const float* spv  = (const float*)d_in[16];
    float* out = (float*)d_out;

    const int smemB = (int)sizeof(SmemB);
    cudaFuncSetAttribute(kB, cudaFuncAttributeMaxDynamicSharedMemorySize, smemB);

    kA<<<dim3(256, 16), 256>>>(obs, emb, WihF, WihB, bihF, bhhF, bihB, bhhB);
    kB<<<64, 512, smemB>>>(WhhF, WhhB, h0, c0);
    kS<<<256, 256>>>(Wlin, blin);
    kC<<<64, 512>>>(pw, stv, spv, out);
}

// round 7
// speedup vs baseline: 1.1886x; 1.1886x over previous
#include <cuda_runtime.h>
#include <cuda_bf16.h>
#include <math.h>

typedef unsigned long long ull;

// ---------------- constants ----------------
#define T_LEN 512
#define B_SZ  64
#define E_DIM 256
#define H_DIM 256
#define S_ST  64
#define G4H   1024   // 4*H

// ---------------- device scratch ----------------
__device__ float g_xg[2][T_LEN][B_SZ][G4H];   // precomputed x-gates + bias (chain-step order)
__device__ float g_h[T_LEN * B_SZ][2 * H_DIM]; // BiLSTM features
__device__ float g_sc[T_LEN * B_SZ][S_ST];     // emission scores (incl b_lin)

// ---------------- helpers ----------------
__device__ __forceinline__ ull pk2(float x, float y) {
    ull r; asm("mov.b64 %0, {%1,%2};" : "=l"(r) : "f"(x), "f"(y)); return r;
}
__device__ __forceinline__ void upk2(ull v, float& x, float& y) {
    asm("mov.b64 {%0,%1}, %2;" : "=f"(x), "=f"(y) : "l"(v));
}
__device__ __forceinline__ ull fma2_(ull a, ull b, ull c) {
    ull d; asm("fma.rn.f32x2 %0, %1, %2, %3;" : "=l"(d) : "l"(a), "l"(b), "l"(c)); return d;
}
__device__ __forceinline__ ull add2_(ull a, ull b) {
    ull d; asm("add.rn.f32x2 %0, %1, %2;" : "=l"(d) : "l"(a), "l"(b)); return d;
}
__device__ __forceinline__ unsigned smem_u32(const void* p) {
    unsigned a;
    asm("{ .reg .u64 t; cvta.to.shared.u64 t, %1; cvt.u32.u64 %0, t; }" : "=r"(a) : "l"(p));
    return a;
}
__device__ __forceinline__ unsigned mapa_(unsigned addr, unsigned rank) {
    unsigned r; asm("mapa.shared::cluster.u32 %0, %1, %2;" : "=r"(r) : "r"(addr), "r"(rank));
    return r;
}
#define CLUSTER_SYNC() do { \
    asm volatile("barrier.cluster.arrive.aligned;" ::: "memory"); \
    asm volatile("barrier.cluster.wait.aligned;"   ::: "memory"); \
} while (0)

#define MBAR_INIT(addr, cnt) \
    asm volatile("mbarrier.init.shared.b64 [%0], %1;" :: "r"(addr), "r"(cnt) : "memory")
#define MBAR_INVAL(addr) \
    asm volatile("mbarrier.inval.shared.b64 [%0];" :: "r"(addr) : "memory")
#define MBAR_EXPECT_TX(addr, tx) \
    asm volatile("mbarrier.arrive.expect_tx.shared.b64 _, [%0], %1;" \
                 :: "r"(addr), "r"(tx) : "memory")
#define MBAR_ARRIVE_CLUSTER(raddr) \
    asm volatile("mbarrier.arrive.shared::cluster.b64 _, [%0];" :: "r"(raddr) : "memory")

#define MBAR_WAIT(addr, parity) do { \
    unsigned _mb = (addr); unsigned _ph = (parity); unsigned _done; \
    asm volatile("{\n\t.reg .pred p;\n\t" \
        "mbarrier.try_wait.parity.acquire.cta.shared::cta.b64 p, [%1], %2;\n\t" \
        "selp.b32 %0, 1, 0, p;\n\t}" : "=r"(_done) : "r"(_mb), "r"(_ph) : "memory"); \
    if (!_done) { \
        asm volatile("{\n\t.reg .pred P1;\n\t" \
            "WL_%=:\n\t" \
            "mbarrier.try_wait.parity.acquire.cta.shared::cta.b64 P1, [%0], %1, 0x989680;\n\t" \
            "@P1 bra.uni WD_%=;\n\t" \
            "bra.uni WL_%=;\n\t" \
            "WD_%=:\n\t}" :: "r"(_mb), "r"(_ph) : "memory"); \
    } \
} while (0)

#define BULK_S2S(dst, src, bytes, mbar) \
    asm volatile("cp.async.bulk.shared::cluster.shared::cta.mbarrier::complete_tx::bytes " \
                 "[%0], [%1], %2, [%3];" \
                 :: "r"(dst), "r"(src), "r"(bytes), "r"(mbar) : "memory")

__device__ __forceinline__ float sgm(float x) { return 1.0f / (1.0f + expf(-x)); }
__device__ __forceinline__ float tanh_(float x) { return 1.0f - 2.0f / (expf(2.0f * x) + 1.0f); }

// =====================================================================
// Kernel A: x-gates GEMM, BM=128/BN=64/BK=32, 8x4 micro, register
// double-buffered global loads (LDG latency hidden behind compute).
// =====================================================================
__global__ void __launch_bounds__(256) kA(
    const int* __restrict__ obs, const float* __restrict__ emb,
    const float* __restrict__ WihF, const float* __restrict__ WihB,
    const float* __restrict__ bihF, const float* __restrict__ bhhF,
    const float* __restrict__ bihB, const float* __restrict__ bhhB)
{
    __shared__ float As[32][132];
    __shared__ float Bs[32][68];
    __shared__ int rowidx[128];

    const int tid = threadIdx.x;
    const int mBase = blockIdx.x * 128;
    const int nTile = blockIdx.y;            // 0..31
    const int dir = nTile >> 4;
    const int nBase = (nTile & 15) * 64;
    const float* W = dir ? WihB : WihF;

    if (tid < 128) rowidx[tid] = obs[mBase + tid];
    __syncthreads();

    const int ty = tid >> 4;
    const int tx = tid & 15;

    ull acc[4][4];
#pragma unroll
    for (int m = 0; m < 4; m++)
#pragma unroll
        for (int j = 0; j < 4; j++) acc[m][j] = 0ull;

    const int arow = tid >> 3, akq = tid & 7;
    const int bn = tid >> 2, bkq = tid & 3;

    // prefetch kt=0 into registers
    float4 pa[4], pb[2];
#pragma unroll
    for (int rr = 0; rr < 4; ++rr)
        pa[rr] = *reinterpret_cast<const float4*>(
            &emb[(size_t)rowidx[arow + rr * 32] * E_DIM + akq * 4]);
#pragma unroll
    for (int hh = 0; hh < 2; ++hh)
        pb[hh] = *reinterpret_cast<const float4*>(
            &W[(size_t)(nBase + bn) * E_DIM + bkq * 8 + hh * 4]);

    for (int kt = 0; kt < 8; ++kt) {
        // store current tile regs -> smem (K-major)
#pragma unroll
        for (int rr = 0; rr < 4; ++rr) {
            int r = arow + rr * 32;
            As[akq * 4 + 0][r] = pa[rr].x; As[akq * 4 + 1][r] = pa[rr].y;
            As[akq * 4 + 2][r] = pa[rr].z; As[akq * 4 + 3][r] = pa[rr].w;
        }
#pragma unroll
        for (int hh = 0; hh < 2; ++hh) {
            Bs[bkq * 8 + hh * 4 + 0][bn] = pb[hh].x; Bs[bkq * 8 + hh * 4 + 1][bn] = pb[hh].y;
            Bs[bkq * 8 + hh * 4 + 2][bn] = pb[hh].z; Bs[bkq * 8 + hh * 4 + 3][bn] = pb[hh].w;
        }
        __syncthreads();

        // issue next tile loads (latency hidden behind compute below)
        if (kt < 7) {
            const int kn = (kt + 1) * 32;
#pragma unroll
            for (int rr = 0; rr < 4; ++rr)
                pa[rr] = *reinterpret_cast<const float4*>(
                    &emb[(size_t)rowidx[arow + rr * 32] * E_DIM + kn + akq * 4]);
#pragma unroll
            for (int hh = 0; hh < 2; ++hh)
                pb[hh] = *reinterpret_cast<const float4*>(
                    &W[(size_t)(nBase + bn) * E_DIM + kn + bkq * 8 + hh * 4]);
        }

#pragma unroll 8
        for (int k = 0; k < 32; ++k) {
            float4 a0 = *reinterpret_cast<const float4*>(&As[k][ty * 8]);
            float4 a1 = *reinterpret_cast<const float4*>(&As[k][ty * 8 + 4]);
            float4 b4 = *reinterpret_cast<const float4*>(&Bs[k][tx * 4]);
            ull ap[4] = {pk2(a0.x, a0.y), pk2(a0.z, a0.w), pk2(a1.x, a1.y), pk2(a1.z, a1.w)};
            ull bd[4] = {pk2(b4.x, b4.x), pk2(b4.y, b4.y), pk2(b4.z, b4.z), pk2(b4.w, b4.w)};
#pragma unroll
            for (int m = 0; m < 4; ++m)
#pragma unroll
                for (int j = 0; j < 4; ++j)
                    acc[m][j] = fma2_(ap[m], bd[j], acc[m][j]);
        }
        __syncthreads();
    }

    const int n0 = nBase + tx * 4;
    const float* bi = dir ? bihB : bihF;
    const float* bh = dir ? bhhB : bhhF;
    float bias[4];
#pragma unroll
    for (int j = 0; j < 4; ++j) bias[j] = bi[n0 + j] + bh[n0 + j];
#pragma unroll
    for (int m = 0; m < 4; ++m) {
        float lo[4], hi[4];
#pragma unroll
        for (int j = 0; j < 4; ++j) upk2(acc[m][j], lo[j], hi[j]);
        int mg0 = mBase + ty * 8 + 2 * m;
#pragma unroll
        for (int r = 0; r < 2; ++r) {
            int mg = mg0 + r;
            int t = mg >> 6, b = mg & 63;
            int sIdx = dir ? (T_LEN - 1 - t) : t;
            const float* src = r ? hi : lo;
            float4 o = make_float4(src[0] + bias[0], src[1] + bias[1],
                                   src[2] + bias[2], src[3] + bias[3]);
            *reinterpret_cast<float4*>(&g_xg[dir][sIdx][b][n0]) = o;
        }
    }
}

// =====================================================================
// Kernel B: recurrence, two interleaved batch-group chains per CTA
// (same dir -> same Whh registers). EXACT R5 version (known good).
// =====================================================================
struct SmemB {
    float hbuf[2][2][H_DIM][8];  // [chain][pingpong][k][batch]   32768 B
    ull   gred[8 * 8 * 64];      // [slot][ksplit][rowpair]       32768 B
    float gfull[8][132];         // gates [batch][row(+pad)]       4224 B
    float hstage[2][2][256];     // [chain][pingpong]              4096 B
    ull   mb_full[2][2];
    ull   mb_go[2][2];
};

__global__ void __launch_bounds__(512, 1) __cluster_dims__(8, 1, 1) kB(
    const float* __restrict__ WhhF, const float* __restrict__ WhhB,
    const float* __restrict__ h0, const float* __restrict__ c0)
{
    extern __shared__ char smraw[];
    SmemB& sm = *reinterpret_cast<SmemB*>(smraw);

    const int tid = threadIdx.x;
    const int blk = blockIdx.x;
    const int cr = blk & 7;
    const int cid = blk >> 3;          // 0..7
    const int dir = cid >> 2;
    const int bgp = cid & 3;
    const int b0[2] = { bgp * 16, bgp * 16 + 8 };
    const float* Whh = dir ? WhhB : WhhF;
    const float* xg = &g_xg[dir][0][0][0];

    // ---- GEMV role ----
    const int c = tid >> 6;
    const int rp = tid & 63;
    const int jA = 2 * rp, jB = 2 * rp + 1;
    const int rgA = ((jA >> 5) << 8) + (cr << 5) + (jA & 31);
    const int rgB = ((jB >> 5) << 8) + (cr << 5) + (jB & 31);

    float wA[32], wB[32];
    {
        const float4* pA = reinterpret_cast<const float4*>(&Whh[(size_t)rgA * H_DIM + 32 * c]);
        const float4* pB = reinterpret_cast<const float4*>(&Whh[(size_t)rgB * H_DIM + 32 * c]);
#pragma unroll
        for (int qq = 0; qq < 8; ++qq) {
            float4 va = pA[qq], vb = pB[qq];
            wA[qq * 4 + 0] = va.x; wA[qq * 4 + 1] = va.y; wA[qq * 4 + 2] = va.z; wA[qq * 4 + 3] = va.w;
            wB[qq * 4 + 0] = vb.x; wB[qq * 4 + 1] = vb.y; wB[qq * 4 + 2] = vb.z; wB[qq * 4 + 3] = vb.w;
        }
    }

    // ---- output/reduce role ----
    const int slot = tid >> 6;
    const int rpo = tid & 63;
    const int jOut = 2 * rpo + (slot >> 2);
    const int mOut = slot & 3;
    const int rgOut = ((jOut >> 5) << 8) + (cr << 5) + (jOut & 31);
    const float* pXg0[2] = {
        xg + ((size_t)(b0[0] + 2 * mOut)) * G4H + rgOut,
        xg + ((size_t)(b0[1] + 2 * mOut)) * G4H + rgOut };

    // ---- init hbuf[ch][0] with h0 ----
    for (int idx = tid; idx < 4096; idx += 512) {
        int ch = idx >> 11, r2 = idx & 2047;
        int k = r2 >> 3, bb = r2 & 7;
        sm.hbuf[ch][0][k][bb] = h0[((size_t)dir * B_SZ + b0[ch] + bb) * H_DIM + k];
    }

    // ---- cell role ----
    const int u = tid >> 3, bb = tid & 7;
    float c_reg[2] = {0.f, 0.f};
    if (tid < 256) {
        c_reg[0] = c0[((size_t)dir * B_SZ + b0[0] + bb) * H_DIM + cr * 32 + u];
        c_reg[1] = c0[((size_t)dir * B_SZ + b0[1] + bb) * H_DIM + cr * 32 + u];
    }

    // ---- messenger addresses (tid0) ----
    unsigned goL[2][2], fullL[2][2], dstL[2][2];
#pragma unroll
    for (int ch = 0; ch < 2; ++ch)
#pragma unroll
        for (int pp = 0; pp < 2; ++pp) {
            goL[ch][pp]   = smem_u32(&sm.mb_go[ch][pp]);
            fullL[ch][pp] = smem_u32(&sm.mb_full[ch][pp]);
            dstL[ch][pp]  = smem_u32(&sm.hbuf[ch][pp][cr * 32][0]);
        }

    // ---- h gmem store role (tid < 64) ----
    const int sb = tid >> 3, skq = tid & 7;

    if (tid == 0) {
#pragma unroll
        for (int ch = 0; ch < 2; ++ch) {
            MBAR_INIT(fullL[ch][0], 1); MBAR_INIT(fullL[ch][1], 1);
            MBAR_INIT(goL[ch][0], 8);   MBAR_INIT(goL[ch][1], 8);
            MBAR_EXPECT_TX(fullL[ch][1], 7168);   // arm for step-0 pushes
        }
    }
    __syncthreads();
    CLUSTER_SYNC();

    if (tid == 0) {
#pragma unroll
        for (int ch = 0; ch < 2; ++ch)
#pragma unroll
            for (int j = 0; j < 8; ++j)
                MBAR_ARRIVE_CLUSTER(mapa_(goL[ch][1], (unsigned)j));
    }

    unsigned phF[2] = {0, 0};
    unsigned phG[2] = {0, 0};

    for (int s = 0; s < T_LEN; ++s) {
        const int p = s & 1, q = p ^ 1;

#pragma unroll
        for (int ch = 0; ch < 2; ++ch) {
            const unsigned fullLp = fullL[ch][p];

            if (s > 0) {
                MBAR_WAIT(fullLp, (phF[ch] >> p) & 1);
                phF[ch] ^= (1u << p);
            }

            // prefetch xg for output role
            const size_t sOff = (size_t)s * B_SZ * G4H;
            const float xv0 = pXg0[ch][sOff];
            const float xv1 = pXg0[ch][sOff + G4H];

            // ---- GEMV over 32-k chunk, weights in regs ----
            ull aA0 = 0, aA1 = 0, aA2 = 0, aA3 = 0;
            ull aB0 = 0, aB1 = 0, aB2 = 0, aB3 = 0;
            const ulonglong2* hp2 =
                reinterpret_cast<const ulonglong2*>(&sm.hbuf[ch][p][32 * c][0]);
#pragma unroll
            for (int k = 0; k < 32; ++k) {
                ulonglong2 hA = hp2[k * 2 + 0];
                ulonglong2 hB = hp2[k * 2 + 1];
                ull wa = pk2(wA[k], wA[k]);
                ull wb = pk2(wB[k], wB[k]);
                aA0 = fma2_(wa, hA.x, aA0); aA1 = fma2_(wa, hA.y, aA1);
                aA2 = fma2_(wa, hB.x, aA2); aA3 = fma2_(wa, hB.y, aA3);
                aB0 = fma2_(wb, hA.x, aB0); aB1 = fma2_(wb, hA.y, aB1);
                aB2 = fma2_(wb, hB.x, aB2); aB3 = fma2_(wb, hB.y, aB3);
            }
            {
                ull* g = sm.gred;
                g[(0 * 8 + c) * 64 + rp] = aA0;
                g[(1 * 8 + c) * 64 + rp] = aA1;
                g[(2 * 8 + c) * 64 + rp] = aA2;
                g[(3 * 8 + c) * 64 + rp] = aA3;
                g[(4 * 8 + c) * 64 + rp] = aB0;
                g[(5 * 8 + c) * 64 + rp] = aB1;
                g[(6 * 8 + c) * 64 + rp] = aB2;
                g[(7 * 8 + c) * 64 + rp] = aB3;
            }
            __syncthreads();   // all GEMV reads of hbuf[ch][p] done

            if (tid == 0 && s < T_LEN - 1) {
                MBAR_EXPECT_TX(fullLp, 7168);
#pragma unroll
                for (int j = 0; j < 8; ++j)
                    MBAR_ARRIVE_CLUSTER(mapa_(goL[ch][p], (unsigned)j));
            }

            // ---- reduce over 8 k-chunks, add xg, write gates ----
            {
                const ull* g = &sm.gred[(size_t)slot * 8 * 64 + rpo];
                ull r0 = add2_(g[0], g[64]);
                ull r1 = add2_(g[128], g[192]);
                ull r2 = add2_(g[256], g[320]);
                ull r3 = add2_(g[384], g[448]);
                ull r = add2_(add2_(r0, r1), add2_(r2, r3));
                r = add2_(r, pk2(xv0, xv1));
                float lo, hi; upk2(r, lo, hi);
                sm.gfull[2 * mOut][jOut] = lo;
                sm.gfull[2 * mOut + 1][jOut] = hi;
            }
            __syncthreads();

            // ---- LSTM cell (tid < 256) ----
            if (tid < 256) {
                float gi = sm.gfull[bb][u];
                float gf = sm.gfull[bb][32 + u];
                float gg = sm.gfull[bb][64 + u];
                float go = sm.gfull[bb][96 + u];
                float cc = sgm(gf) * c_reg[ch] + sgm(gi) * tanh_(gg);
                c_reg[ch] = cc;
                float hv = sgm(go) * tanh_(cc);
                sm.hstage[ch][p][tid] = hv;
                sm.hbuf[ch][q][cr * 32 + u][bb] = hv;   // self-slice local
            }
            __syncthreads();

            // ---- tid0: async push own slice to 7 peers ----
            if (tid == 0 && s < T_LEN - 1) {
                asm volatile("fence.proxy.async.shared::cta;" ::: "memory");
                MBAR_WAIT(goL[ch][q], (phG[ch] >> q) & 1);
                phG[ch] ^= (1u << q);
                const unsigned src = smem_u32(&sm.hstage[ch][p][0]);
#pragma unroll
                for (int j = 0; j < 8; ++j) {
                    if (j == cr) continue;
                    unsigned dst = mapa_(dstL[ch][q], (unsigned)j);
                    unsigned mb = mapa_(fullL[ch][q], (unsigned)j);
                    BULK_S2S(dst, src, 1024u, mb);
                }
            }

            // ---- h to gmem for score GEMM (tid < 64) ----
            if (tid < 64) {
                float4 o;
                o.x = sm.hstage[ch][p][(skq * 4 + 0) * 8 + sb];
                o.y = sm.hstage[ch][p][(skq * 4 + 1) * 8 + sb];
                o.z = sm.hstage[ch][p][(skq * 4 + 2) * 8 + sb];
                o.w = sm.hstage[ch][p][(skq * 4 + 3) * 8 + sb];
                int tOut = dir ? (T_LEN - 1 - s) : s;
                *reinterpret_cast<float4*>(
                    &g_h[(size_t)tOut * B_SZ + b0[ch] + sb][dir * H_DIM + cr * 32 + skq * 4]) = o;
            }
        }
    }

    CLUSTER_SYNC();
    if (tid == 0) {
#pragma unroll
        for (int ch = 0; ch < 2; ++ch) {
            MBAR_INVAL(fullL[ch][0]); MBAR_INVAL(fullL[ch][1]);
            MBAR_INVAL(goL[ch][0]);   MBAR_INVAL(goL[ch][1]);
        }
    }
}

// =====================================================================
// Kernel S: emission scores GEMM, register double-buffered loads.
// =====================================================================
__global__ void __launch_bounds__(256) kS(
    const float* __restrict__ Wlin, const float* __restrict__ blin)
{
    __shared__ float As[32][132];
    __shared__ float Bs[32][68];

    const int tid = threadIdx.x;
    const int mBase = blockIdx.x * 128;

    const int ty = tid >> 4;
    const int tx = tid & 15;

    ull acc[4][4];
#pragma unroll
    for (int m = 0; m < 4; m++)
#pragma unroll
        for (int j = 0; j < 4; j++) acc[m][j] = 0ull;

    const int arow = tid >> 3, akq = tid & 7;
    const int bn = tid >> 2, bkq = tid & 3;

    float4 pa[4], pb[2];
#pragma unroll
    for (int rr = 0; rr < 4; ++rr)
        pa[rr] = *reinterpret_cast<const float4*>(&g_h[mBase + arow + rr * 32][akq * 4]);
#pragma unroll
    for (int hh = 0; hh < 2; ++hh)
        pb[hh] = *reinterpret_cast<const float4*>(
            &Wlin[(size_t)bn * (2 * H_DIM) + bkq * 8 + hh * 4]);

    for (int kt = 0; kt < 16; ++kt) {
#pragma unroll
        for (int rr = 0; rr < 4; ++rr) {
            int r = arow + rr * 32;
            As[akq * 4 + 0][r] = pa[rr].x; As[akq * 4 + 1][r] = pa[rr].y;
            As[akq * 4 + 2][r] = pa[rr].z; As[akq * 4 + 3][r] = pa[rr].w;
        }
#pragma unroll
        for (int hh = 0; hh < 2; ++hh) {
            Bs[bkq * 8 + hh * 4 + 0][bn] = pb[hh].x; Bs[bkq * 8 + hh * 4 + 1][bn] = pb[hh].y;
            Bs[bkq * 8 + hh * 4 + 2][bn] = pb[hh].z; Bs[bkq * 8 + hh * 4 + 3][bn] = pb[hh].w;
        }
        __syncthreads();

        if (kt < 15) {
            const int kn = (kt + 1) * 32;
#pragma unroll
            for (int rr = 0; rr < 4; ++rr)
                pa[rr] = *reinterpret_cast<const float4*>(
                    &g_h[mBase + arow + rr * 32][kn + akq * 4]);
#pragma unroll
            for (int hh = 0; hh < 2; ++hh)
                pb[hh] = *reinterpret_cast<const float4*>(
                    &Wlin[(size_t)bn * (2 * H_DIM) + kn + bkq * 8 + hh * 4]);
        }

#pragma unroll 8
        for (int k = 0; k < 32; ++k) {
            float4 a0 = *reinterpret_cast<const float4*>(&As[k][ty * 8]);
            float4 a1 = *reinterpret_cast<const float4*>(&As[k][ty * 8 + 4]);
            float4 b4 = *reinterpret_cast<const float4*>(&Bs[k][tx * 4]);
            ull ap[4] = {pk2(a0.x, a0.y), pk2(a0.z, a0.w), pk2(a1.x, a1.y), pk2(a1.z, a1.w)};
            ull bd[4] = {pk2(b4.x, b4.x), pk2(b4.y, b4.y), pk2(b4.z, b4.z), pk2(b4.w, b4.w)};
#pragma unroll
            for (int m = 0; m < 4; ++m)
#pragma unroll
                for (int j = 0; j < 4; ++j)
                    acc[m][j] = fma2_(ap[m], bd[j], acc[m][j]);
        }
        __syncthreads();
    }

    const int n0 = tx * 4;
    float bias[4];
#pragma unroll
    for (int j = 0; j < 4; ++j) bias[j] = blin[n0 + j];
#pragma unroll
    for (int m = 0; m < 4; ++m) {
        float lo[4], hi[4];
#pragma unroll
        for (int j = 0; j < 4; ++j) upk2(acc[m][j], lo[j], hi[j]);
        int row0 = mBase + ty * 8 + 2 * m;
#pragma unroll
        for (int r = 0; r < 2; ++r) {
            const float* src = r ? hi : lo;
            float4 o = make_float4(src[0] + bias[0], src[1] + bias[1],
                                   src[2] + bias[2], src[3] + bias[3]);
            *reinterpret_cast<float4*>(&g_sc[row0 + r][n0]) = o;
        }
    }
}

// =====================================================================
// Kernel C: Viterbi DP + backtrace. R5 shfl merge + 2-deep sc prefetch.
// =====================================================================
__global__ void __launch_bounds__(512) kC(
    const float* __restrict__ pw,
    const float* __restrict__ startv, const float* __restrict__ stopv,
    float* __restrict__ out)
{
    __shared__ float delta[2][64];
    __shared__ float fin[64];
    __shared__ unsigned char bp[T_LEN - 1][64];

    const int b = blockIdx.x;
    const int tid = threadIdx.x;
    const int s = tid >> 3;      // state 0..63
    const int p = tid & 7;       // part 0..7

    float Pr[8];
#pragma unroll
    for (int i = 0; i < 8; ++i) Pr[i] = pw[(p * 8 + i) * 64 + s];

    if (p == 0) delta[0][s] = startv[s] + g_sc[b][s];
    __syncthreads();

    float scA = g_sc[(size_t)1 * B_SZ + b][s];
    float scB = g_sc[(size_t)2 * B_SZ + b][s];
    for (int t = 1; t < T_LEN; ++t) {
        const int pp = (t - 1) & 1, qq = t & 1;
        float4 d0 = *reinterpret_cast<const float4*>(&delta[pp][p * 8]);
        float4 d1 = *reinterpret_cast<const float4*>(&delta[pp][p * 8 + 4]);
        float dv[8] = {d0.x, d0.y, d0.z, d0.w, d1.x, d1.y, d1.z, d1.w};

        float best = dv[0] + Pr[0];
        int bi = p * 8;
#pragma unroll
        for (int i = 1; i < 8; ++i) {
            float v = dv[i] + Pr[i];
            if (v > best) { best = v; bi = p * 8 + i; }
        }
#pragma unroll
        for (int off = 1; off < 8; off <<= 1) {
            float ov = __shfl_xor_sync(0xffffffffu, best, off);
            int oi = __shfl_xor_sync(0xffffffffu, bi, off);
            if (ov > best || (ov == best && oi < bi)) { best = ov; bi = oi; }
        }

        const float sc = scA;
        scA = scB;
        if (t + 2 < T_LEN) scB = g_sc[(size_t)(t + 2) * B_SZ + b][s];

        if (p == 0) {
            bp[t - 1][s] = (unsigned char)bi;
            delta[qq][s] = best + sc;
        }
        __syncthreads();
    }

    if (p == 0) fin[s] = delta[(T_LEN - 1) & 1][s] + stopv[s];
    __syncthreads();

    if (tid == 0) {
        float best = fin[0]; int bi0 = 0;
        for (int i = 1; i < 64; ++i) if (fin[i] > best) { best = fin[i]; bi0 = i; }
        out[b] = best;
        int st = bi0;
        out[64 + (size_t)(T_LEN - 1) * B_SZ + b] = (float)st;
        for (int tt = T_LEN - 2; tt >= 0; --tt) {
            st = bp[tt][st];
            out[64 + (size_t)tt * B_SZ + b] = (float)st;
        }
    }
}

// =====================================================================
extern "C" void kernel_launch(void* const* d_in, const int* in_sizes, int n_in,
                              void* d_out, int out_size)
{
    const int*   obs  = (const int*)  d_in[0];
    const float* h0   = (const float*)d_in[1];
    const float* c0   = (const float*)d_in[2];
    const float* emb  = (const float*)d_in[3];
    const float* WihF = (const float*)d_in[4];
    const float* WhhF = (const float*)d_in[5];
    const float* bihF = (const float*)d_in[6];
    const float* bhhF = (const float*)d_in[7];
    const float* WihB = (const float*)d_in[8];
    const float* WhhB = (const float*)d_in[9];
    const float* bihB = (const float*)d_in[10];
    const float* bhhB = (const float*)d_in[11];
    const float* Wlin = (const float*)d_in[12];
    const float* blin = (const float*)d_in[13];
    const float* pw   = (const float*)d_in[14];
    const float* stv  = (const float*)d_in[15];
    const float* spv  = (const float*)d_in[16];
    float* out = (float*)d_out;

    const int smemB = (int)sizeof(SmemB);
    cudaFuncSetAttribute(kB, cudaFuncAttributeMaxDynamicSharedMemorySize, smemB);

    kA<<<dim3(256, 32), 256>>>(obs, emb, WihF, WihB, bihF, bhhF, bihB, bhhB);
    kB<<<64, 512, smemB>>>(WhhF, WhhB, h0, c0);
    kS<<<256, 256>>>(Wlin, blin);
    kC<<<64, 512>>>(pw, stv, spv, out);
}